// round 4
// baseline (speedup 1.0000x reference)
#include <cuda_runtime.h>
#include <cuda_fp16.h>
#include <cstdint>

// ---------------- problem constants ----------------
#define KTOT   3072
#define NOUT   12288
#define MB     64             // batch (GEMM N side)
#define MTILE  128            // output rows per CTA (GEMM M side)
#define KC     64             // K per chunk
#define NCHUNK (KTOT / KC)    // 48
#define NTH    256
#define NCTA   (NOUT / MTILE) // 96

// smem: B stages 4 x (64 rows x 128B) = 32KB; epilogue transpose area
// [0, 33792) overlaps B after final sync; bias at [33792, 34304).
#define B_ST(s)   ((unsigned)(s) * 8192u)
#define SM_BIAS   33792u
#define EPI_STRIDE 132         // floats per epi row (pad vs 128 to break conflicts)
#define SMEM_TOTAL 34816

// x pre-converted to fp16 (k-major, [64][3072])
__device__ __align__(16) __half g_xh[MB * KTOT];

__global__ void xconv_kernel(const float* __restrict__ x) {
    int i = blockIdx.x * blockDim.x + threadIdx.x;   // indexes float4
    float4 v = ((const float4*)x)[i];
    __half2 h0 = __floats2half2_rn(v.x, v.y);
    __half2 h1 = __floats2half2_rn(v.z, v.w);
    uint2 r;
    r.x = *reinterpret_cast<uint32_t*>(&h0);
    r.y = *reinterpret_cast<uint32_t*>(&h1);
    ((uint2*)g_xh)[i] = r;
}

// ---------------- device helpers ----------------
__device__ __forceinline__ uint32_t smem_u32(const void* p) {
    uint32_t a;
    asm("{ .reg .u64 t; cvta.to.shared.u64 t, %1; cvt.u32.u64 %0, t; }" : "=r"(a) : "l"(p));
    return a;
}
__device__ __forceinline__ uint32_t swz(uint32_t off) {  // SW128 Swizzle<3,4,3>
    return off ^ ((off >> 3) & 0x70u);
}
__device__ __forceinline__ void cp_async16(uint32_t dst, const void* src) {
    asm volatile("cp.async.cg.shared.global [%0], [%1], 16;"
                 :: "r"(dst), "l"(src) : "memory");
}
#define CP_COMMIT()  asm volatile("cp.async.commit_group;" ::: "memory")
#define CP_WAIT(n)   asm volatile("cp.async.wait_group %0;" :: "n"(n) : "memory")

__device__ __forceinline__ void ldsm4(uint32_t& r0, uint32_t& r1, uint32_t& r2, uint32_t& r3,
                                      uint32_t addr) {
    asm volatile("ldmatrix.sync.aligned.m8n8.x4.shared.b16 {%0,%1,%2,%3}, [%4];"
                 : "=r"(r0), "=r"(r1), "=r"(r2), "=r"(r3) : "r"(addr));
}
__device__ __forceinline__ void mma16816(float* c,
                                         uint32_t a0, uint32_t a1, uint32_t a2, uint32_t a3,
                                         uint32_t b0, uint32_t b1) {
    asm volatile(
        "mma.sync.aligned.m16n8k16.row.col.f32.f16.f16.f32 "
        "{%0,%1,%2,%3}, {%4,%5,%6,%7}, {%8,%9}, {%0,%1,%2,%3};"
        : "+f"(c[0]), "+f"(c[1]), "+f"(c[2]), "+f"(c[3])
        : "r"(a0), "r"(a1), "r"(a2), "r"(a3), "r"(b0), "r"(b1));
}
// dequant 2 int32 codes -> packed half2: (code - 128) * s
__device__ __forceinline__ uint32_t dq2(int2 cd, float s) {
    const float o = -128.0f * s;
    float f0 = fmaf((float)cd.x, s, o);
    float f1 = fmaf((float)cd.y, s, o);
    __half2 h = __floats2half2_rn(f0, f1);
    return *reinterpret_cast<uint32_t*>(&h);
}

__global__ __launch_bounds__(NTH, 1)
void dql_kernel(const int*   __restrict__ wq,
                const float* __restrict__ ws,
                const int*   __restrict__ bq,
                const float* __restrict__ bs,
                float*       __restrict__ out) {
    extern __shared__ __align__(1024) char smem[];
    const uint32_t sb = smem_u32(smem);
    float* smf = (float*)smem;

    const int tid  = threadIdx.x;
    const int lane = tid & 31;
    const int wm   = tid >> 5;      // warp 0..7, owns rows [wm*16, wm*16+16)
    const int cta  = blockIdx.x;

    // ---- bias precompute into smem ----
    if (tid < MTILE) {
        const int o = cta * MTILE + tid;
        ((float*)(smem + SM_BIAS))[tid] = ((float)bq[o] - 128.0f) * bs[o >> 5];
    }

    // ---- A fragment-direct load mapping ----
    const int r1 = cta * MTILE + wm * 16 + (lane >> 2);   // fragment row
    const int tq = (lane & 3) * 2;                        // k sub-offset
    const int*    w1  = wq + (size_t)r1 * KTOT;
    const int*    w2  = w1 + 8 * KTOT;
    const float2* s1p = (const float2*)(ws + (size_t)r1 * (KTOT / 32));
    const float2* s2p = (const float2*)(ws + (size_t)(r1 + 8) * (KTOT / 32));

    int2   ar[2][16];
    float2 sr[2][2];

    // ---- B cp.async mapping ----
    const int brow  = tid >> 2;         // 0..63
    const int bseg0 = tid & 3;          // segments bseg0 and bseg0+4
    const char* xsrc = (const char*)(g_xh + (size_t)brow * KTOT);

    auto issueB = [&](int c) {
        const uint32_t dbase = sb + B_ST(c & 3);
        const char* s = xsrc + (size_t)c * (KC * 2);
#pragma unroll
        for (int j = 0; j < 2; j++) {
            const int seg = bseg0 + j * 4;
            cp_async16(dbase + swz((uint32_t)(brow * 128 + seg * 16)), s + seg * 16);
        }
    };
    auto g2rA = [&](int c, int buf) {
        const int kb = c * KC;
#pragma unroll
        for (int ks = 0; ks < 4; ks++) {
            const int k = kb + ks * 16 + tq;
            ar[buf][ks * 4 + 0] = *(const int2*)(w1 + k);
            ar[buf][ks * 4 + 1] = *(const int2*)(w2 + k);
            ar[buf][ks * 4 + 2] = *(const int2*)(w1 + k + 8);
            ar[buf][ks * 4 + 3] = *(const int2*)(w2 + k + 8);
        }
        sr[buf][0] = s1p[c];
        sr[buf][1] = s2p[c];
    };

    float acc[8][4];
#pragma unroll
    for (int nf = 0; nf < 8; nf++)
#pragma unroll
        for (int i = 0; i < 4; i++) acc[nf][i] = 0.0f;

    // ---- prologue: 3 B stages in flight, 2 A chunks in regs ----
    issueB(0); CP_COMMIT();
    issueB(1); CP_COMMIT();
    issueB(2); CP_COMMIT();
    g2rA(0, 0);
    g2rA(1, 1);

    // ldmatrix B lane addressing (warp-independent; 4 groups of 16 n-rows)
    const uint32_t b_lrow = (uint32_t)((lane & 7) + ((lane >> 4) & 1) * 8);
    const uint32_t b_lcol = (uint32_t)(((lane >> 3) & 1) * 16);

    for (int c = 0; c < NCHUNK; c++) {
        const int buf = c & 1;
        CP_WAIT(2);          // B(c) complete (3 + c groups committed so far)
        __syncthreads();     // B(c) visible to all; stage (c+3)%4 free of readers

        if (c + 3 < NCHUNK) issueB(c + 3);
        CP_COMMIT();         // always commit to keep wait_group arithmetic

        // dequant A chunk c into fp16 fragments
        uint32_t af[16];
        {
            const float s1a = sr[buf][0].x, s1b = sr[buf][0].y;
            const float s2a = sr[buf][1].x, s2b = sr[buf][1].y;
#pragma unroll
            for (int ks = 0; ks < 4; ks++) {
                const float s1 = (ks < 2) ? s1a : s1b;
                const float s2 = (ks < 2) ? s2a : s2b;
                af[ks * 4 + 0] = dq2(ar[buf][ks * 4 + 0], s1);
                af[ks * 4 + 1] = dq2(ar[buf][ks * 4 + 1], s2);
                af[ks * 4 + 2] = dq2(ar[buf][ks * 4 + 2], s1);
                af[ks * 4 + 3] = dq2(ar[buf][ks * 4 + 3], s2);
            }
        }
        if (c + 2 < NCHUNK) g2rA(c + 2, buf);   // refill the buffer just consumed

        // compute
        const uint32_t Bs = sb + B_ST(c & 3);
#pragma unroll
        for (int ks = 0; ks < 4; ks++) {
            uint32_t b[4][4];
#pragma unroll
            for (int u = 0; u < 4; u++) {
                const uint32_t addr = Bs + swz((u * 16 + b_lrow) * 128 +
                                               (uint32_t)(ks * 32) + b_lcol);
                ldsm4(b[u][0], b[u][1], b[u][2], b[u][3], addr);
            }
#pragma unroll
            for (int nf = 0; nf < 8; nf++) {
                const int u = nf >> 1;
                const int p = (nf & 1) * 2;
                mma16816(acc[nf],
                         af[ks * 4 + 0], af[ks * 4 + 1], af[ks * 4 + 2], af[ks * 4 + 3],
                         b[u][p], b[u][p + 1]);
            }
        }
    }

    // ---- epilogue: smem transpose + bias + coalesced stores ----
    __syncthreads();   // everyone done with B stages before overwrite
    {
        const int o = wm * 16 + (lane >> 2);
#pragma unroll
        for (int nf = 0; nf < 8; nf++) {
            const int m = nf * 8 + (lane & 3) * 2;
            smf[(m)     * EPI_STRIDE + o]     = acc[nf][0];
            smf[(m + 1) * EPI_STRIDE + o]     = acc[nf][1];
            smf[(m)     * EPI_STRIDE + o + 8] = acc[nf][2];
            smf[(m + 1) * EPI_STRIDE + o + 8] = acc[nf][3];
        }
    }
    __syncthreads();
    {
        const int m = tid >> 2;
        const int q = tid & 3;
        const float*  row   = smf + (size_t)m * EPI_STRIDE;
        const float4* bias4 = (const float4*)(smem + SM_BIAS);
        float* op = out + (size_t)m * NOUT + cta * MTILE;
#pragma unroll
        for (int j = 0; j < 8; j++) {
            const int ol = q * 32 + j * 4;
            float4 v = *(const float4*)(row + ol);
            float4 bb = bias4[ol >> 2];
            v.x += bb.x; v.y += bb.y; v.z += bb.z; v.w += bb.w;
            *(float4*)(op + ol) = v;
        }
    }
}

extern "C" void kernel_launch(void* const* d_in, const int* in_sizes, int n_in,
                              void* d_out, int out_size) {
    (void)in_sizes; (void)n_in; (void)out_size;
    xconv_kernel<<<(MB * KTOT / 4) / NTH, NTH>>>((const float*)d_in[0]);
    dql_kernel<<<NCTA, NTH, SMEM_TOTAL>>>(
        (const int*)d_in[1],     // w_q
        (const float*)d_in[2],   // w_scales
        (const int*)d_in[3],     // b_q
        (const float*)d_in[4],   // b_scales
        (float*)d_out);
}

// round 6
// speedup vs baseline: 1.8142x; 1.8142x over previous
#include <cuda_runtime.h>
#include <cuda_fp16.h>
#include <cstdint>

// ---------------- problem constants ----------------
#define KTOT   3072
#define NOUT   12288
#define MB     64             // batch (GEMM N side)
#define MTILE  32             // output rows per CTA (GEMM M side)
#define KC     64             // K per chunk
#define NCHUNK (KTOT / KC)    // 48
#define NTH    256
#define NCTA   (NOUT / MTILE) // 384

// ---- stage layout (4 stages) ----
// A codes: 32 rows x 72 ints (padded from 64) = 9216 B   at +0
// B tile : 64 rows x 128 B (SW128 swizzled)   = 8192 B   at +9216
// scales : 32 rows x float2                   = 256  B   at +17408
#define SM_B      9216u
#define SM_S      17408u
#define ST_STRIDE 17920u
#define SM_BIAS   71680u            // 4*ST_STRIDE
#define EPI_STRIDE 36               // floats per epi row (144B, 16B-aligned)
#define SMEM_TOTAL 71936            // 71680 + 128 bias + pad

// x pre-converted to fp16 (k-major, [64][3072])
__device__ __align__(16) __half g_xh[MB * KTOT];

__global__ void xconv_kernel(const float* __restrict__ x) {
    int i = blockIdx.x * blockDim.x + threadIdx.x;   // indexes float4
    float4 v = ((const float4*)x)[i];
    __half2 h0 = __floats2half2_rn(v.x, v.y);
    __half2 h1 = __floats2half2_rn(v.z, v.w);
    uint2 r;
    r.x = *reinterpret_cast<uint32_t*>(&h0);
    r.y = *reinterpret_cast<uint32_t*>(&h1);
    ((uint2*)g_xh)[i] = r;
}

// ---------------- device helpers ----------------
__device__ __forceinline__ uint32_t smem_u32(const void* p) {
    uint32_t a;
    asm("{ .reg .u64 t; cvta.to.shared.u64 t, %1; cvt.u32.u64 %0, t; }" : "=r"(a) : "l"(p));
    return a;
}
__device__ __forceinline__ uint32_t swz(uint32_t off) {  // SW128 Swizzle<3,4,3>
    return off ^ ((off >> 3) & 0x70u);
}
__device__ __forceinline__ void cp_async16(uint32_t dst, const void* src) {
    asm volatile("cp.async.cg.shared.global [%0], [%1], 16;"
                 :: "r"(dst), "l"(src) : "memory");
}
__device__ __forceinline__ void cp_async8(uint32_t dst, const void* src) {
    asm volatile("cp.async.ca.shared.global [%0], [%1], 8;"
                 :: "r"(dst), "l"(src) : "memory");
}
#define CP_COMMIT()  asm volatile("cp.async.commit_group;" ::: "memory")
#define CP_WAIT(n)   asm volatile("cp.async.wait_group %0;" :: "n"(n) : "memory")

__device__ __forceinline__ void ldsm4(uint32_t& r0, uint32_t& r1, uint32_t& r2, uint32_t& r3,
                                      uint32_t addr) {
    asm volatile("ldmatrix.sync.aligned.m8n8.x4.shared.b16 {%0,%1,%2,%3}, [%4];"
                 : "=r"(r0), "=r"(r1), "=r"(r2), "=r"(r3) : "r"(addr));
}
__device__ __forceinline__ void mma16816(float* c,
                                         uint32_t a0, uint32_t a1, uint32_t a2, uint32_t a3,
                                         uint32_t b0, uint32_t b1) {
    asm volatile(
        "mma.sync.aligned.m16n8k16.row.col.f32.f16.f16.f32 "
        "{%0,%1,%2,%3}, {%4,%5,%6,%7}, {%8,%9}, {%0,%1,%2,%3};"
        : "+f"(c[0]), "+f"(c[1]), "+f"(c[2]), "+f"(c[3])
        : "r"(a0), "r"(a1), "r"(a2), "r"(a3), "r"(b0), "r"(b1));
}
// dequant 2 int32 codes -> packed half2: (code - 128) * s
__device__ __forceinline__ uint32_t dq2(int2 cd, float s) {
    const float o = -128.0f * s;
    float f0 = fmaf((float)cd.x, s, o);
    float f1 = fmaf((float)cd.y, s, o);
    __half2 h = __floats2half2_rn(f0, f1);
    return *reinterpret_cast<uint32_t*>(&h);
}

__global__ __launch_bounds__(NTH, 3)
void dql_kernel(const int*   __restrict__ wq,
                const float* __restrict__ ws,
                const int*   __restrict__ bq,
                const float* __restrict__ bs,
                float*       __restrict__ out) {
    extern __shared__ __align__(16) char smem[];
    const uint32_t sb = smem_u32(smem);
    float* smf = (float*)smem;

    const int tid  = threadIdx.x;
    const int lane = tid & 31;
    const int wid  = tid >> 5;
    const int wm   = wid & 1;      // warp M slab (rows wm*16 .. +16)
    const int wn   = wid >> 1;     // warp N slab (batch wn*16 .. +16)
    const int cta  = blockIdx.x;

    // bias for this CTA's 32 output rows
    if (tid < MTILE) {
        const int o = cta * MTILE + tid;
        ((float*)(smem + SM_BIAS))[tid] = ((float)bq[o] - 128.0f) * bs[o >> 5];
    }

    // ---- cp.async producer mappings ----
    const int a_r   = tid >> 3;                 // 0..31 (weight row)
    const int a_seg = tid & 7;                  // 16B segment
    const char* a_src0 = (const char*)(wq + (size_t)(cta * MTILE + a_r) * KTOT) + a_seg * 16;
    const int brow  = tid >> 2;                 // 0..63 (batch row)
    const int bseg  = tid & 3;
    const char* b_src0 = (const char*)(g_xh + (size_t)brow * KTOT) + bseg * 16;
    const char* s_src0 = (const char*)(ws + (size_t)(cta * MTILE + tid) * (KTOT / 32));

    auto issueStage = [&](int c) {
        const uint32_t st = sb + (uint32_t)(c & 3) * ST_STRIDE;
        // A codes: 32 rows x 256B (each thread: two 16B segs of one row)
        {
            const char* s = a_src0 + (size_t)c * 256;   // 64 ints = 256B per row-chunk
            const uint32_t d = st + (uint32_t)(a_r * 288 + a_seg * 16);
            cp_async16(d, s);
            cp_async16(d + 128, s + 128);
        }
        // B tile: 64 rows x 128B swizzled
        {
            const char* s = b_src0 + (size_t)c * (KC * 2);
            cp_async16(st + SM_B + swz((uint32_t)(brow * 128 + bseg * 16)), s + 0);
            cp_async16(st + SM_B + swz((uint32_t)(brow * 128 + (bseg + 4) * 16)),
                       s + 64);
        }
        // scales: 32 rows x float2
        if (tid < MTILE) {
            cp_async8(st + SM_S + (uint32_t)(tid * 8), s_src0 + (size_t)c * 8);
        }
    };

    float acc[2][4];
#pragma unroll
    for (int nf = 0; nf < 2; nf++)
#pragma unroll
        for (int i = 0; i < 4; i++) acc[nf][i] = 0.0f;

    // ---- consumer addressing ----
    const int fr  = wm * 16 + (lane >> 2);      // fragment row (local, 0..31)
    const int tq  = (lane & 3) * 2;             // k sub-offset
    const uint32_t b_lrow = (uint32_t)(wn * 16 + (lane & 7) + ((lane >> 4) & 1) * 8);
    const uint32_t b_lcol = (uint32_t)(((lane >> 3) & 1) * 16);

    // ---- prologue: 3 stages in flight ----
    issueStage(0); CP_COMMIT();
    issueStage(1); CP_COMMIT();
    issueStage(2); CP_COMMIT();

    for (int c = 0; c < NCHUNK; c++) {
        CP_WAIT(2);
        __syncthreads();                 // stage c ready; stage (c+3)&3 free

        if (c + 3 < NCHUNK) issueStage(c + 3);
        CP_COMMIT();

        const uint32_t stOff = (uint32_t)(c & 3) * ST_STRIDE;
        const char* As = smem + stOff;
        const uint32_t Bs = sb + stOff + SM_B;

        // per-row scales (float2: .x for k-block 0, .y for k-block 1)
        const float2 s0 = *(const float2*)(smem + stOff + SM_S + fr * 8);
        const float2 s1 = *(const float2*)(smem + stOff + SM_S + (fr + 8) * 8);

#pragma unroll
        for (int ks = 0; ks < 4; ks++) {
            const int k0 = ks * 16 + tq;
            const float sa = (ks < 2) ? s0.x : s0.y;
            const float sbb = (ks < 2) ? s1.x : s1.y;
            int2 c00 = *(const int2*)(As + (fr * 288      + k0 * 4));
            int2 c10 = *(const int2*)(As + ((fr + 8) * 288 + k0 * 4));
            int2 c01 = *(const int2*)(As + (fr * 288      + (k0 + 8) * 4));
            int2 c11 = *(const int2*)(As + ((fr + 8) * 288 + (k0 + 8) * 4));
            uint32_t a0 = dq2(c00, sa);
            uint32_t a1 = dq2(c10, sbb);
            uint32_t a2 = dq2(c01, sa);
            uint32_t a3 = dq2(c11, sbb);

            uint32_t b0, b1, b2, b3;
            ldsm4(b0, b1, b2, b3,
                  Bs + swz(b_lrow * 128 + (uint32_t)(ks * 32) + b_lcol));

            mma16816(acc[0], a0, a1, a2, a3, b0, b1);
            mma16816(acc[1], a0, a1, a2, a3, b2, b3);
        }
    }

    // ---- epilogue: smem transpose + bias + coalesced stores ----
    __syncthreads();
    {
        const int o = wm * 16 + (lane >> 2);
#pragma unroll
        for (int nf = 0; nf < 2; nf++) {
            const int m = wn * 16 + nf * 8 + (lane & 3) * 2;
            smf[(m)     * EPI_STRIDE + o]     = acc[nf][0];
            smf[(m + 1) * EPI_STRIDE + o]     = acc[nf][1];
            smf[(m)     * EPI_STRIDE + o + 8] = acc[nf][2];
            smf[(m + 1) * EPI_STRIDE + o + 8] = acc[nf][3];
        }
    }
    __syncthreads();
    {
        const int m = tid >> 2;          // 0..63
        const int q = tid & 3;           // 8-float segment
        const float* row  = smf + (size_t)m * EPI_STRIDE + q * 8;
        const float* bias = (const float*)(smem + SM_BIAS) + q * 8;
        float* op = out + (size_t)m * NOUT + cta * MTILE + q * 8;
        float4 v0 = *(const float4*)(row);
        float4 v1 = *(const float4*)(row + 4);
        float4 b0 = *(const float4*)(bias);
        float4 b1 = *(const float4*)(bias + 4);
        v0.x += b0.x; v0.y += b0.y; v0.z += b0.z; v0.w += b0.w;
        v1.x += b1.x; v1.y += b1.y; v1.z += b1.z; v1.w += b1.w;
        *(float4*)(op)     = v0;
        *(float4*)(op + 4) = v1;
    }
}

extern "C" void kernel_launch(void* const* d_in, const int* in_sizes, int n_in,
                              void* d_out, int out_size) {
    (void)in_sizes; (void)n_in; (void)out_size;
    xconv_kernel<<<(MB * KTOT / 4) / NTH, NTH>>>((const float*)d_in[0]);
    cudaFuncSetAttribute(dql_kernel, cudaFuncAttributeMaxDynamicSharedMemorySize, SMEM_TOTAL);
    dql_kernel<<<NCTA, NTH, SMEM_TOTAL>>>(
        (const int*)d_in[1],     // w_q
        (const float*)d_in[2],   // w_scales
        (const int*)d_in[3],     // b_q
        (const float*)d_in[4],   // b_scales
        (float*)d_out);
}

// round 7
// speedup vs baseline: 2.2058x; 1.2159x over previous
#include <cuda_runtime.h>
#include <cuda_fp16.h>
#include <cstdint>

// ---------------- problem constants ----------------
#define KTOT   3072
#define NOUT   12288
#define MB     64             // batch (GEMM N side)
#define MTILE  32             // output rows per CTA
#define KC     64             // K per chunk
#define NCHUNK (KTOT / KC)    // 48
#define NTH    256
#define NCTA   (NOUT / MTILE) // 384

// ---- stage layout (4 stages) ----
// A codes : 32 rows x 256 B (raw int32)        at +0
// B tile  : 64 rows x 128 B (fp16, SW128)      at +8192
// scales  : 32 rows x float2                    at +16384
#define SM_B      8192u
#define SM_S      16384u
#define ST_STRIDE 16640u
#define AF_OFF    66560u      // 4*ST_STRIDE ; 2 x 4096B fp16 A tiles
#define SM_BIAS   74752u      // AF_OFF + 8192
#define SMEM_TOTAL 74880u
#define EPI_RSTRIDE 33        // floats per row in epilogue warp region

// x pre-converted to fp16 (k-major, [64][3072])
__device__ __align__(16) __half g_xh[MB * KTOT];

__global__ void xconv_kernel(const float* __restrict__ x) {
    int i = blockIdx.x * blockDim.x + threadIdx.x;   // indexes float4
    float4 v = ((const float4*)x)[i];
    __half2 h0 = __floats2half2_rn(v.x, v.y);
    __half2 h1 = __floats2half2_rn(v.z, v.w);
    uint2 r;
    r.x = *reinterpret_cast<uint32_t*>(&h0);
    r.y = *reinterpret_cast<uint32_t*>(&h1);
    ((uint2*)g_xh)[i] = r;
}

// ---------------- device helpers ----------------
__device__ __forceinline__ uint32_t smem_u32(const void* p) {
    uint32_t a;
    asm("{ .reg .u64 t; cvta.to.shared.u64 t, %1; cvt.u32.u64 %0, t; }" : "=r"(a) : "l"(p));
    return a;
}
__device__ __forceinline__ uint32_t swz(uint32_t off) {  // SW128 Swizzle<3,4,3>
    return off ^ ((off >> 3) & 0x70u);
}
__device__ __forceinline__ void cp_async16(uint32_t dst, const void* src) {
    asm volatile("cp.async.cg.shared.global [%0], [%1], 16;"
                 :: "r"(dst), "l"(src) : "memory");
}
__device__ __forceinline__ void cp_async8(uint32_t dst, const void* src) {
    asm volatile("cp.async.ca.shared.global [%0], [%1], 8;"
                 :: "r"(dst), "l"(src) : "memory");
}
#define CP_COMMIT()  asm volatile("cp.async.commit_group;" ::: "memory")
#define CP_WAIT(n)   asm volatile("cp.async.wait_group %0;" :: "n"(n) : "memory")

__device__ __forceinline__ void sts64(uint32_t addr, uint32_t a, uint32_t b) {
    asm volatile("st.shared.v2.b32 [%0], {%1, %2};" :: "r"(addr), "r"(a), "r"(b) : "memory");
}
__device__ __forceinline__ void ldsm4(uint32_t* r, uint32_t addr) {
    asm volatile("ldmatrix.sync.aligned.m8n8.x4.shared.b16 {%0,%1,%2,%3}, [%4];"
                 : "=r"(r[0]), "=r"(r[1]), "=r"(r[2]), "=r"(r[3]) : "r"(addr));
}
__device__ __forceinline__ void mma16816(float* c,
                                         uint32_t a0, uint32_t a1, uint32_t a2, uint32_t a3,
                                         uint32_t b0, uint32_t b1) {
    asm volatile(
        "mma.sync.aligned.m16n8k16.row.col.f32.f16.f16.f32 "
        "{%0,%1,%2,%3}, {%4,%5,%6,%7}, {%8,%9}, {%0,%1,%2,%3};"
        : "+f"(c[0]), "+f"(c[1]), "+f"(c[2]), "+f"(c[3])
        : "r"(a0), "r"(a1), "r"(a2), "r"(a3), "r"(b0), "r"(b1));
}

__global__ __launch_bounds__(NTH, 3)
void dql_kernel(const int*   __restrict__ wq,
                const float* __restrict__ ws,
                const int*   __restrict__ bq,
                const float* __restrict__ bs,
                float*       __restrict__ out) {
    extern __shared__ __align__(16) char smem[];
    const uint32_t sb = smem_u32(smem);
    float* smf = (float*)smem;

    const int tid  = threadIdx.x;
    const int lane = tid & 31;
    const int wid  = tid >> 5;
    const int wk   = wid >> 1;     // k-split quarter (16 k per warp per chunk)
    const int wn   = wid & 1;      // batch half (32)
    const int cta  = blockIdx.x;

    // bias for this CTA's 32 output rows
    if (tid < MTILE) {
        const int o = cta * MTILE + tid;
        ((float*)(smem + SM_BIAS))[tid] = ((float)bq[o] - 128.0f) * bs[o >> 5];
    }

    // ---- cp.async producer mappings ----
    const int a_r   = tid >> 3;                 // 0..31 (weight row)
    const int a_seg = tid & 7;                  // 16B segment (two: a_seg, a_seg+8)
    const char* a_src0 = (const char*)(wq + (size_t)(cta * MTILE + a_r) * KTOT) + a_seg * 16;
    const int brow  = tid >> 2;                 // 0..63 (batch row)
    const int bseg  = tid & 3;
    const char* b_src0 = (const char*)(g_xh + (size_t)brow * KTOT) + bseg * 16;
    const char* s_src0 = (const char*)(ws + (size_t)(cta * MTILE + tid) * (KTOT / 32));

    auto issueStage = [&](int c) {
        const uint32_t st = sb + (uint32_t)(c & 3) * ST_STRIDE;
        {   // A codes raw: 32 rows x 256B
            const char* s = a_src0 + (size_t)c * 256;
            const uint32_t d = st + (uint32_t)(a_r * 256 + a_seg * 16);
            cp_async16(d, s);
            cp_async16(d + 128, s + 128);
        }
        {   // B fp16 tile, SW128 swizzled
            const char* s = b_src0 + (size_t)c * (KC * 2);
            cp_async16(st + SM_B + swz((uint32_t)(brow * 128 + bseg * 16)), s);
            cp_async16(st + SM_B + swz((uint32_t)(brow * 128 + (bseg + 4) * 16)), s + 64);
        }
        if (tid < MTILE) {  // scales float2 per row
            cp_async8(st + SM_S + (uint32_t)(tid * 8), s_src0 + (size_t)c * 8);
        }
    };

    float acc[2][4][4];
#pragma unroll
    for (int mf = 0; mf < 2; mf++)
#pragma unroll
        for (int nf = 0; nf < 4; nf++)
#pragma unroll
            for (int i = 0; i < 4; i++) acc[mf][nf][i] = 0.0f;

    // ---- cooperative dequant mapping: thread -> (rows r1, r1+16; k-quad u) ----
    const int dq_r = tid >> 4;      // 0..15
    const int dq_u = tid & 15;      // k 4u..4u+3
    const __half2 c1152 = __half2(__ushort_as_half((unsigned short)0x6480),
                                  __ushort_as_half((unsigned short)0x6480));

    // ---- consumer ldmatrix addressing ----
    const uint32_t a_lrow = (uint32_t)(lane & 15);
    const uint32_t a_lcol = (uint32_t)(((lane >> 4) & 1) * 16);
    const uint32_t b_lrow = (uint32_t)(wn * 32 + (lane & 7) + ((lane >> 4) & 1) * 8);
    const uint32_t b_lcol = (uint32_t)(((lane >> 3) & 1) * 16);
    const uint32_t kcol   = (uint32_t)(wk * 32);   // this warp's 16-k window (32B)

    // ---- prologue: 3 stages in flight ----
    issueStage(0); CP_COMMIT();
    issueStage(1); CP_COMMIT();
    issueStage(2); CP_COMMIT();

    for (int c = 0; c < NCHUNK; c++) {
        CP_WAIT(2);
        __syncthreads();                 // stage c ready; stage (c+3)&3 free

        if (c + 3 < NCHUNK) issueStage(c + 3);
        CP_COMMIT();

        const uint32_t stOff = (uint32_t)(c & 3) * ST_STRIDE;
        const uint32_t AF    = sb + AF_OFF + (uint32_t)(c & 1) * 4096u;

        // ---- cooperative dequant: codes -> fp16 A tile (each code once) ----
#pragma unroll
        for (int j = 0; j < 2; j++) {
            const int row = dq_r + 16 * j;
            int4 cd = *(const int4*)(smem + stOff + row * 256 + dq_u * 16);
            float s = *(const float*)(smem + stOff + SM_S + row * 8 + (dq_u >> 3) * 4);
            __half2 s2 = __float2half2_rn(s);
            uint32_t lo = __byte_perm((uint32_t)cd.x, (uint32_t)cd.y, 0x3430) | 0x64006400u;
            uint32_t hi = __byte_perm((uint32_t)cd.z, (uint32_t)cd.w, 0x3430) | 0x64006400u;
            __half2 v0 = __hmul2(__hsub2(*(__half2*)&lo, c1152), s2);
            __half2 v1 = __hmul2(__hsub2(*(__half2*)&hi, c1152), s2);
            sts64(AF + swz((uint32_t)(row * 128 + dq_u * 8)),
                  *(uint32_t*)&v0, *(uint32_t*)&v1);
        }
        __syncthreads();                 // fp16 A tile ready

        // ---- ldsm + mma (this warp: 32 rows x 32 batch x 16 k) ----
        const uint32_t Bs = sb + stOff + SM_B;
        uint32_t a[2][4], b[2][4];
#pragma unroll
        for (int mf = 0; mf < 2; mf++)
            ldsm4(a[mf], AF + swz((uint32_t)((mf * 16) * 128) + a_lrow * 128 + kcol + a_lcol));
#pragma unroll
        for (int nf2 = 0; nf2 < 2; nf2++)
            ldsm4(b[nf2], Bs + swz((b_lrow + (uint32_t)(nf2 * 16)) * 128 + kcol + b_lcol));
#pragma unroll
        for (int mf = 0; mf < 2; mf++)
#pragma unroll
            for (int nf = 0; nf < 4; nf++) {
                const int u = nf >> 1;
                const int p = (nf & 1) * 2;
                mma16816(acc[mf][nf], a[mf][0], a[mf][1], a[mf][2], a[mf][3],
                         b[u][p], b[u][p + 1]);
            }
    }

    // ---- epilogue: per-warp partials -> smem, reduce over wk, bias, store ----
    __syncthreads();
    {
        const uint32_t wbase = (uint32_t)(wid * 32 * EPI_RSTRIDE);
        const int g = lane >> 2;
        const int q = (lane & 3) * 2;
#pragma unroll
        for (int mf = 0; mf < 2; mf++)
#pragma unroll
            for (int nf = 0; nf < 4; nf++) {
                const int row = mf * 16 + g;
                const int col = nf * 8 + q;
                smf[wbase + row * EPI_RSTRIDE + col]            = acc[mf][nf][0];
                smf[wbase + row * EPI_RSTRIDE + col + 1]        = acc[mf][nf][1];
                smf[wbase + (row + 8) * EPI_RSTRIDE + col]      = acc[mf][nf][2];
                smf[wbase + (row + 8) * EPI_RSTRIDE + col + 1]  = acc[mf][nf][3];
            }
    }
    __syncthreads();
    {
        const int row = tid & 31;
        const int mg  = tid >> 5;
        const float bias = ((const float*)(smem + SM_BIAS))[row];
        float* op = out + (size_t)cta * MTILE + row;
#pragma unroll
        for (int j = 0; j < 8; j++) {
            const int m  = mg * 8 + j;
            const int wn_ = m >> 5;
            const int ml  = m & 31;
            float v = bias;
#pragma unroll
            for (int k4 = 0; k4 < 4; k4++)
                v += smf[(uint32_t)((k4 * 2 + wn_) * 32 * EPI_RSTRIDE + row * EPI_RSTRIDE + ml)];
            op[(size_t)m * NOUT] = v;
        }
    }
}

extern "C" void kernel_launch(void* const* d_in, const int* in_sizes, int n_in,
                              void* d_out, int out_size) {
    (void)in_sizes; (void)n_in; (void)out_size;
    xconv_kernel<<<(MB * KTOT / 4) / NTH, NTH>>>((const float*)d_in[0]);
    cudaFuncSetAttribute(dql_kernel, cudaFuncAttributeMaxDynamicSharedMemorySize, SMEM_TOTAL);
    dql_kernel<<<NCTA, NTH, SMEM_TOTAL>>>(
        (const int*)d_in[1],     // w_q
        (const float*)d_in[2],   // w_scales
        (const int*)d_in[3],     // b_q
        (const float*)d_in[4],   // b_scales
        (float*)d_out);
}

// round 8
// speedup vs baseline: 2.2313x; 1.0116x over previous
#include <cuda_runtime.h>
#include <cuda_fp16.h>
#include <cstdint>

// ---------------- problem constants ----------------
#define KTOT   3072
#define NOUT   12288
#define MB     64             // batch (GEMM N side)
#define MTILE  32             // output rows per CTA
#define KC     64             // K per chunk
#define NCHUNK (KTOT / KC)    // 48
#define NTH    256
#define NCTA   (NOUT / MTILE) // 384

// ---- stage layout (4 stages) ----
// A codes : 32 rows x 256 B (raw int32)        at +0
// B tile  : 64 rows x 128 B (fp16, SW128)      at +8192
// scales  : 32 rows x float2                    at +16384
#define SM_B      8192u
#define SM_S      16384u
#define ST_STRIDE 16640u
#define AF_OFF    66560u      // 4*ST_STRIDE ; 2 x 4096B fp16 A tiles
#define SM_BIAS   74752u      // AF_OFF + 8192
#define SMEM_TOTAL 74880u
#define EPI_RSTRIDE 33        // floats per row in epilogue warp region

// x pre-converted to fp16 (k-major, [64][3072])
__device__ __align__(16) __half g_xh[MB * KTOT];

__global__ void xconv_kernel(const float* __restrict__ x) {
    int i = blockIdx.x * blockDim.x + threadIdx.x;   // indexes float4
    float4 v = ((const float4*)x)[i];
    __half2 h0 = __floats2half2_rn(v.x, v.y);
    __half2 h1 = __floats2half2_rn(v.z, v.w);
    uint2 r;
    r.x = *reinterpret_cast<uint32_t*>(&h0);
    r.y = *reinterpret_cast<uint32_t*>(&h1);
    ((uint2*)g_xh)[i] = r;
}

// ---------------- device helpers ----------------
__device__ __forceinline__ uint32_t smem_u32(const void* p) {
    uint32_t a;
    asm("{ .reg .u64 t; cvta.to.shared.u64 t, %1; cvt.u32.u64 %0, t; }" : "=r"(a) : "l"(p));
    return a;
}
__device__ __forceinline__ uint32_t swz(uint32_t off) {  // SW128 Swizzle<3,4,3>
    return off ^ ((off >> 3) & 0x70u);
}
__device__ __forceinline__ void cp_async16(uint32_t dst, const void* src) {
    asm volatile("cp.async.cg.shared.global [%0], [%1], 16;"
                 :: "r"(dst), "l"(src) : "memory");
}
__device__ __forceinline__ void cp_async8(uint32_t dst, const void* src) {
    asm volatile("cp.async.ca.shared.global [%0], [%1], 8;"
                 :: "r"(dst), "l"(src) : "memory");
}
#define CP_COMMIT()  asm volatile("cp.async.commit_group;" ::: "memory")
#define CP_WAIT(n)   asm volatile("cp.async.wait_group %0;" :: "n"(n) : "memory")

__device__ __forceinline__ void sts64(uint32_t addr, uint32_t a, uint32_t b) {
    asm volatile("st.shared.v2.b32 [%0], {%1, %2};" :: "r"(addr), "r"(a), "r"(b) : "memory");
}
__device__ __forceinline__ void ldsm4(uint32_t* r, uint32_t addr) {
    asm volatile("ldmatrix.sync.aligned.m8n8.x4.shared.b16 {%0,%1,%2,%3}, [%4];"
                 : "=r"(r[0]), "=r"(r[1]), "=r"(r[2]), "=r"(r[3]) : "r"(addr));
}
__device__ __forceinline__ void mma16816(float* c,
                                         uint32_t a0, uint32_t a1, uint32_t a2, uint32_t a3,
                                         uint32_t b0, uint32_t b1) {
    asm volatile(
        "mma.sync.aligned.m16n8k16.row.col.f32.f16.f16.f32 "
        "{%0,%1,%2,%3}, {%4,%5,%6,%7}, {%8,%9}, {%0,%1,%2,%3};"
        : "+f"(c[0]), "+f"(c[1]), "+f"(c[2]), "+f"(c[3])
        : "r"(a0), "r"(a1), "r"(a2), "r"(a3), "r"(b0), "r"(b1));
}

__global__ __launch_bounds__(NTH, 3)
void dql_kernel(const int*   __restrict__ wq,
                const float* __restrict__ ws,
                const int*   __restrict__ bq,
                const float* __restrict__ bs,
                float*       __restrict__ out) {
    extern __shared__ __align__(16) char smem[];
    const uint32_t sb = smem_u32(smem);
    float* smf = (float*)smem;

    const int tid  = threadIdx.x;
    const int lane = tid & 31;
    const int wid  = tid >> 5;
    const int wk   = wid >> 1;     // k-split quarter (16 k per warp per chunk)
    const int wn   = wid & 1;      // batch half (32)
    const int cta  = blockIdx.x;

    // bias for this CTA's 32 output rows
    if (tid < MTILE) {
        const int o = cta * MTILE + tid;
        ((float*)(smem + SM_BIAS))[tid] = ((float)bq[o] - 128.0f) * bs[o >> 5];
    }

    // ---- cp.async producer mappings ----
    const int a_r   = tid >> 3;                 // 0..31 (weight row)
    const int a_seg = tid & 7;                  // 16B segment (two: a_seg, a_seg+8)
    const char* a_src0 = (const char*)(wq + (size_t)(cta * MTILE + a_r) * KTOT) + a_seg * 16;
    const int brow  = tid >> 2;                 // 0..63 (batch row)
    const int bseg  = tid & 3;
    const char* b_src0 = (const char*)(g_xh + (size_t)brow * KTOT) + bseg * 16;
    const char* s_src0 = (const char*)(ws + (size_t)(cta * MTILE + tid) * (KTOT / 32));

    auto issueStage = [&](int c) {
        const uint32_t st = sb + (uint32_t)(c & 3) * ST_STRIDE;
        {   // A codes raw: 32 rows x 256B
            const char* s = a_src0 + (size_t)c * 256;
            const uint32_t d = st + (uint32_t)(a_r * 256 + a_seg * 16);
            cp_async16(d, s);
            cp_async16(d + 128, s + 128);
        }
        {   // B fp16 tile, SW128 swizzled
            const char* s = b_src0 + (size_t)c * (KC * 2);
            cp_async16(st + SM_B + swz((uint32_t)(brow * 128 + bseg * 16)), s);
            cp_async16(st + SM_B + swz((uint32_t)(brow * 128 + (bseg + 4) * 16)), s + 64);
        }
        if (tid < MTILE) {  // scales float2 per row
            cp_async8(st + SM_S + (uint32_t)(tid * 8), s_src0 + (size_t)c * 8);
        }
    };

    // ---- cooperative dequant mapping: thread -> (rows r, r+16; k-quad u) ----
    const int dq_r = tid >> 4;      // 0..15
    const int dq_u = tid & 15;      // k 4u..4u+3
    const __half2 c1152 = __half2(__ushort_as_half((unsigned short)0x6480),
                                  __ushort_as_half((unsigned short)0x6480));

    auto dequant = [&](int c) {     // codes of stage (c&3) -> fp16 tile AF[c&1]
        const uint32_t stOff = (uint32_t)(c & 3) * ST_STRIDE;
        const uint32_t AF    = sb + AF_OFF + (uint32_t)(c & 1) * 4096u;
#pragma unroll
        for (int j = 0; j < 2; j++) {
            const int row = dq_r + 16 * j;
            int4 cd = *(const int4*)(smem + stOff + row * 256 + dq_u * 16);
            float s = *(const float*)(smem + stOff + SM_S + row * 8 + (dq_u >> 3) * 4);
            __half2 s2 = __float2half2_rn(s);
            uint32_t lo = __byte_perm((uint32_t)cd.x, (uint32_t)cd.y, 0x3430) | 0x64006400u;
            uint32_t hi = __byte_perm((uint32_t)cd.z, (uint32_t)cd.w, 0x3430) | 0x64006400u;
            __half2 v0 = __hmul2(__hsub2(*(__half2*)&lo, c1152), s2);
            __half2 v1 = __hmul2(__hsub2(*(__half2*)&hi, c1152), s2);
            sts64(AF + swz((uint32_t)(row * 128 + dq_u * 8)),
                  *(uint32_t*)&v0, *(uint32_t*)&v1);
        }
    };

    float acc[2][4][4];
#pragma unroll
    for (int mf = 0; mf < 2; mf++)
#pragma unroll
        for (int nf = 0; nf < 4; nf++)
#pragma unroll
            for (int i = 0; i < 4; i++) acc[mf][nf][i] = 0.0f;

    // ---- consumer ldmatrix addressing ----
    const uint32_t a_lrow = (uint32_t)(lane & 15);
    const uint32_t a_lcol = (uint32_t)(((lane >> 4) & 1) * 16);
    const uint32_t b_lrow = (uint32_t)(wn * 32 + (lane & 7) + ((lane >> 4) & 1) * 8);
    const uint32_t b_lcol = (uint32_t)(((lane >> 3) & 1) * 16);
    const uint32_t kcol   = (uint32_t)(wk * 32);   // this warp's 16-k window (32B)

    // ---- prologue: 3 stages in flight; dequant AF(0) ----
    issueStage(0); CP_COMMIT();
    issueStage(1); CP_COMMIT();
    issueStage(2); CP_COMMIT();
    CP_WAIT(2);                      // stage 0 complete
    __syncthreads();
    dequant(0);

    for (int c = 0; c < NCHUNK; c++) {
        CP_WAIT(1);                  // stage c+1 complete (commits = 3 + c)
        __syncthreads();             // AF(c) visible; slot (c+3)&3 free of readers

        if (c + 3 < NCHUNK) issueStage(c + 3);
        CP_COMMIT();

        if (c + 1 < NCHUNK) dequant(c + 1);   // off the mma dependency path

        // ---- ldsm + mma on AF(c), B(c) ----
        const uint32_t stOff = (uint32_t)(c & 3) * ST_STRIDE;
        const uint32_t AF    = sb + AF_OFF + (uint32_t)(c & 1) * 4096u;
        const uint32_t Bs    = sb + stOff + SM_B;
        uint32_t a[2][4], b[2][4];
#pragma unroll
        for (int mf = 0; mf < 2; mf++)
            ldsm4(a[mf], AF + swz((uint32_t)((mf * 16) * 128) + a_lrow * 128 + kcol + a_lcol));
#pragma unroll
        for (int nf2 = 0; nf2 < 2; nf2++)
            ldsm4(b[nf2], Bs + swz((b_lrow + (uint32_t)(nf2 * 16)) * 128 + kcol + b_lcol));
#pragma unroll
        for (int mf = 0; mf < 2; mf++)
#pragma unroll
            for (int nf = 0; nf < 4; nf++) {
                const int u = nf >> 1;
                const int p = (nf & 1) * 2;
                mma16816(acc[mf][nf], a[mf][0], a[mf][1], a[mf][2], a[mf][3],
                         b[u][p], b[u][p + 1]);
            }
    }

    // ---- epilogue: per-warp partials -> smem, reduce over wk, bias, store ----
    __syncthreads();
    {
        const uint32_t wbase = (uint32_t)(wid * 32 * EPI_RSTRIDE);
        const int g = lane >> 2;
        const int q = (lane & 3) * 2;
#pragma unroll
        for (int mf = 0; mf < 2; mf++)
#pragma unroll
            for (int nf = 0; nf < 4; nf++) {
                const int row = mf * 16 + g;
                const int col = nf * 8 + q;
                smf[wbase + row * EPI_RSTRIDE + col]            = acc[mf][nf][0];
                smf[wbase + row * EPI_RSTRIDE + col + 1]        = acc[mf][nf][1];
                smf[wbase + (row + 8) * EPI_RSTRIDE + col]      = acc[mf][nf][2];
                smf[wbase + (row + 8) * EPI_RSTRIDE + col + 1]  = acc[mf][nf][3];
            }
    }
    __syncthreads();
    {
        const int row = tid & 31;
        const int mg  = tid >> 5;
        const float bias = ((const float*)(smem + SM_BIAS))[row];
        float* op = out + (size_t)cta * MTILE + row;
#pragma unroll
        for (int j = 0; j < 8; j++) {
            const int m  = mg * 8 + j;
            const int wn_ = m >> 5;
            const int ml  = m & 31;
            float v = bias;
#pragma unroll
            for (int k4 = 0; k4 < 4; k4++)
                v += smf[(uint32_t)((k4 * 2 + wn_) * 32 * EPI_RSTRIDE + row * EPI_RSTRIDE + ml)];
            op[(size_t)m * NOUT] = v;
        }
    }
}

extern "C" void kernel_launch(void* const* d_in, const int* in_sizes, int n_in,
                              void* d_out, int out_size) {
    (void)in_sizes; (void)n_in; (void)out_size;
    xconv_kernel<<<(MB * KTOT / 4) / NTH, NTH>>>((const float*)d_in[0]);
    cudaFuncSetAttribute(dql_kernel, cudaFuncAttributeMaxDynamicSharedMemorySize, SMEM_TOTAL);
    dql_kernel<<<NCTA, NTH, SMEM_TOTAL>>>(
        (const int*)d_in[1],     // w_q
        (const float*)d_in[2],   // w_scales
        (const int*)d_in[3],     // b_q
        (const float*)d_in[4],   // b_scales
        (float*)d_out);
}

// round 9
// speedup vs baseline: 2.2953x; 1.0287x over previous
#include <cuda_runtime.h>
#include <cuda_fp16.h>
#include <cstdint>

// ---------------- problem constants ----------------
#define KTOT   3072
#define NOUT   12288
#define MB     64             // batch (GEMM N side)
#define MTILE  32             // output rows per CTA
#define KC     64             // K per chunk
#define NCHUNK (KTOT / KC)    // 48
#define NTH    256
#define NCTA   (NOUT / MTILE) // 384

// ---- stage layout (3 stages) ----
// A codes : 32 rows x 256 B (int32, XOR-swizzled int2 positions) at +0
// B tile  : 64 rows x 128 B (fp16, SW128)                        at +8192
// scales  : 32 rows x float2                                      at +16384
#define SM_B      8192u
#define SM_S      16384u
#define ST_STRIDE 16640u
#define SM_BIAS   49920u      // 3*ST_STRIDE
#define SMEM_TOTAL 50176u
#define EPI_RSTRIDE 33        // floats per row in epilogue warp region

// x pre-converted to fp16 (k-major, [64][3072])
__device__ __align__(16) __half g_xh[MB * KTOT];

__global__ void xconv_kernel(const float* __restrict__ x) {
    int i = blockIdx.x * blockDim.x + threadIdx.x;   // indexes float4
    float4 v = ((const float4*)x)[i];
    __half2 h0 = __floats2half2_rn(v.x, v.y);
    __half2 h1 = __floats2half2_rn(v.z, v.w);
    uint2 r;
    r.x = *reinterpret_cast<uint32_t*>(&h0);
    r.y = *reinterpret_cast<uint32_t*>(&h1);
    ((uint2*)g_xh)[i] = r;
}

// ---------------- device helpers ----------------
__device__ __forceinline__ uint32_t smem_u32(const void* p) {
    uint32_t a;
    asm("{ .reg .u64 t; cvta.to.shared.u64 t, %1; cvt.u32.u64 %0, t; }" : "=r"(a) : "l"(p));
    return a;
}
__device__ __forceinline__ uint32_t swz(uint32_t off) {  // SW128 Swizzle<3,4,3>
    return off ^ ((off >> 3) & 0x70u);
}
__device__ __forceinline__ void cp_async16(uint32_t dst, const void* src) {
    asm volatile("cp.async.cg.shared.global [%0], [%1], 16;"
                 :: "r"(dst), "l"(src) : "memory");
}
__device__ __forceinline__ void cp_async8(uint32_t dst, const void* src) {
    asm volatile("cp.async.ca.shared.global [%0], [%1], 8;"
                 :: "r"(dst), "l"(src) : "memory");
}
#define CP_COMMIT()  asm volatile("cp.async.commit_group;" ::: "memory")
#define CP_WAIT(n)   asm volatile("cp.async.wait_group %0;" :: "n"(n) : "memory")

__device__ __forceinline__ void ldsm4(uint32_t* r, uint32_t addr) {
    asm volatile("ldmatrix.sync.aligned.m8n8.x4.shared.b16 {%0,%1,%2,%3}, [%4];"
                 : "=r"(r[0]), "=r"(r[1]), "=r"(r[2]), "=r"(r[3]) : "r"(addr));
}
__device__ __forceinline__ void lds64(uint32_t& x, uint32_t& y, uint32_t addr) {
    asm volatile("ld.shared.v2.b32 {%0,%1}, [%2];" : "=r"(x), "=r"(y) : "r"(addr));
}
__device__ __forceinline__ void mma16816(float* c,
                                         uint32_t a0, uint32_t a1, uint32_t a2, uint32_t a3,
                                         uint32_t b0, uint32_t b1) {
    asm volatile(
        "mma.sync.aligned.m16n8k16.row.col.f32.f16.f16.f32 "
        "{%0,%1,%2,%3}, {%4,%5,%6,%7}, {%8,%9}, {%0,%1,%2,%3};"
        : "+f"(c[0]), "+f"(c[1]), "+f"(c[2]), "+f"(c[3])
        : "r"(a0), "r"(a1), "r"(a2), "r"(a3), "r"(b0), "r"(b1));
}

__global__ __launch_bounds__(NTH, 4)
void dql_kernel(const int*   __restrict__ wq,
                const float* __restrict__ ws,
                const int*   __restrict__ bq,
                const float* __restrict__ bs,
                float*       __restrict__ out) {
    extern __shared__ __align__(16) char smem[];
    const uint32_t sb = smem_u32(smem);
    float* smf = (float*)smem;

    const int tid  = threadIdx.x;
    const int lane = tid & 31;
    const int wid  = tid >> 5;
    const int wk   = wid >> 1;     // k-split quarter (16 k per warp per chunk)
    const int wn   = wid & 1;      // batch half (32)
    const int cta  = blockIdx.x;

    // bias for this CTA's 32 output rows
    if (tid < MTILE) {
        const int o = cta * MTILE + tid;
        ((float*)(smem + SM_BIAS))[tid] = ((float)bq[o] - 128.0f) * bs[o >> 5];
    }

    // ---- cp.async producer mappings ----
    const int a_r   = tid >> 3;                 // 0..31 (weight row)
    const int a_seg = tid & 7;                  // 16B segment (covers a_seg, a_seg+8)
    const char* a_src0 = (const char*)(wq + (size_t)(cta * MTILE + a_r) * KTOT) + a_seg * 16;
    // XOR-swizzled int2 positions within the 256B code row
    const uint32_t a_e   = (uint32_t)((a_r & 7) << 2);
    const uint32_t a_d0  = (uint32_t)(a_r * 256) + (((uint32_t)(2 * a_seg)      ^ a_e) * 8);
    const uint32_t a_d1  = (uint32_t)(a_r * 256) + (((uint32_t)(2 * a_seg + 16) ^ a_e) * 8);
    const int brow  = tid >> 2;                 // 0..63 (batch row)
    const int bseg  = tid & 3;
    const char* b_src0 = (const char*)(g_xh + (size_t)brow * KTOT) + bseg * 16;
    const char* s_src0 = (const char*)(ws + (size_t)(cta * MTILE + tid) * (KTOT / 32));

    auto issueStage = [&](int c) {
        const uint32_t st = sb + (uint32_t)(c % 3) * ST_STRIDE;
        {   // A codes: 32 rows x 256B, swizzled placement
            const char* s = a_src0 + (size_t)c * 256;
            cp_async16(st + a_d0, s);
            cp_async16(st + a_d1, s + 128);
        }
        {   // B fp16 tile, SW128 swizzled
            const char* s = b_src0 + (size_t)c * (KC * 2);
            cp_async16(st + SM_B + swz((uint32_t)(brow * 128 + bseg * 16)), s);
            cp_async16(st + SM_B + swz((uint32_t)(brow * 128 + (bseg + 4) * 16)), s + 64);
        }
        if (tid < MTILE) {  // scales float2 per row
            cp_async8(st + SM_S + (uint32_t)(tid * 8), s_src0 + (size_t)c * 8);
        }
    };

    float acc[2][4][4];
#pragma unroll
    for (int mf = 0; mf < 2; mf++)
#pragma unroll
        for (int nf = 0; nf < 4; nf++)
#pragma unroll
            for (int i = 0; i < 4; i++) acc[mf][nf][i] = 0.0f;

    // ---- consumer addressing ----
    const int r      = lane >> 2;                  // fragment base row
    const int k2base = wk * 8 + (lane & 3);        // int2 index within 32
    const int kb4    = (wk >> 1) * 4;              // scale byte sel within float2
    const uint32_t b_lrow = (uint32_t)(wn * 32 + (lane & 7) + ((lane >> 4) & 1) * 8);
    const uint32_t b_lcol = (uint32_t)(((lane >> 3) & 1) * 16);
    const uint32_t kcol   = (uint32_t)(wk * 32);   // this warp's 16-k window (32B)
    const __half2 c1152 = __half2(__ushort_as_half((unsigned short)0x6480),
                                  __ushort_as_half((unsigned short)0x6480));

    // ---- prologue: 2 stages in flight ----
    issueStage(0); CP_COMMIT();
    issueStage(1); CP_COMMIT();

    for (int c = 0; c < NCHUNK; c++) {
        CP_WAIT(1);                  // stage c complete (commits = c+2 here)
        __syncthreads();             // visibility; slot (c+2)%3 readers done

        if (c + 2 < NCHUNK) issueStage(c + 2);
        CP_COMMIT();

        const uint32_t stOff = (uint32_t)(c % 3) * ST_STRIDE;
        const uint32_t As = sb + stOff;
        const uint32_t Ss = sb + stOff + SM_S;
        const uint32_t Bs = sb + stOff + SM_B;

        // ---- dequant codes -> A fragments in registers ----
        uint32_t a[2][4];
#pragma unroll
        for (int j = 0; j < 4; j++) {
            const int R = r + 8 * j;
            float s;
            asm volatile("ld.shared.f32 %0, [%1];" : "=f"(s)
                         : "r"(Ss + (uint32_t)(R * 8 + kb4)));
            const __half2 s2 = __float2half2_rn(s);
            const uint32_t rowb = As + (uint32_t)(R * 256);
            const uint32_t e    = (uint32_t)((R & 7) << 2);
#pragma unroll
            for (int h = 0; h < 2; h++) {
                const uint32_t k2 = (uint32_t)(k2base + 4 * h);
                uint32_t cx, cy;
                lds64(cx, cy, rowb + ((k2 ^ e) * 8));
                uint32_t v = __byte_perm(cx, cy, 0x3430) | 0x64006400u;
                __half2 hv = __hmul2(__hsub2(*(__half2*)&v, c1152), s2);
                a[j >> 1][(j & 1) + 2 * h] = *(uint32_t*)&hv;
            }
        }

        // ---- B fragments + mma ----
        uint32_t b[2][4];
#pragma unroll
        for (int nf2 = 0; nf2 < 2; nf2++)
            ldsm4(b[nf2], Bs + swz((b_lrow + (uint32_t)(nf2 * 16)) * 128 + kcol + b_lcol));
#pragma unroll
        for (int mf = 0; mf < 2; mf++)
#pragma unroll
            for (int nf = 0; nf < 4; nf++) {
                const int u = nf >> 1;
                const int p = (nf & 1) * 2;
                mma16816(acc[mf][nf], a[mf][0], a[mf][1], a[mf][2], a[mf][3],
                         b[u][p], b[u][p + 1]);
            }
    }

    // ---- epilogue: per-warp partials -> smem, reduce over wk, bias, store ----
    __syncthreads();
    {
        const uint32_t wbase = (uint32_t)(wid * 32 * EPI_RSTRIDE);
        const int g = lane >> 2;
        const int q = (lane & 3) * 2;
#pragma unroll
        for (int mf = 0; mf < 2; mf++)
#pragma unroll
            for (int nf = 0; nf < 4; nf++) {
                const int row = mf * 16 + g;
                const int col = nf * 8 + q;
                smf[wbase + row * EPI_RSTRIDE + col]            = acc[mf][nf][0];
                smf[wbase + row * EPI_RSTRIDE + col + 1]        = acc[mf][nf][1];
                smf[wbase + (row + 8) * EPI_RSTRIDE + col]      = acc[mf][nf][2];
                smf[wbase + (row + 8) * EPI_RSTRIDE + col + 1]  = acc[mf][nf][3];
            }
    }
    __syncthreads();
    {
        const int row = tid & 31;
        const int mg  = tid >> 5;
        const float bias = ((const float*)(smem + SM_BIAS))[row];
        float* op = out + (size_t)cta * MTILE + row;
#pragma unroll
        for (int j = 0; j < 8; j++) {
            const int m  = mg * 8 + j;
            const int wn_ = m >> 5;
            const int ml  = m & 31;
            float v = bias;
#pragma unroll
            for (int k4 = 0; k4 < 4; k4++)
                v += smf[(uint32_t)((k4 * 2 + wn_) * 32 * EPI_RSTRIDE + row * EPI_RSTRIDE + ml)];
            op[(size_t)m * NOUT] = v;
        }
    }
}

extern "C" void kernel_launch(void* const* d_in, const int* in_sizes, int n_in,
                              void* d_out, int out_size) {
    (void)in_sizes; (void)n_in; (void)out_size;
    xconv_kernel<<<(MB * KTOT / 4) / NTH, NTH>>>((const float*)d_in[0]);
    cudaFuncSetAttribute(dql_kernel, cudaFuncAttributeMaxDynamicSharedMemorySize, SMEM_TOTAL);
    dql_kernel<<<NCTA, NTH, SMEM_TOTAL>>>(
        (const int*)d_in[1],     // w_q
        (const float*)d_in[2],   // w_scales
        (const int*)d_in[3],     // b_q
        (const float*)d_in[4],   // b_scales
        (float*)d_out);
}